// round 12
// baseline (speedup 1.0000x reference)
#include <cuda_runtime.h>
#include <cuda_bf16.h>
#include <stdint.h>

// SimplifiedMambaBlock == identity on x (scan is multiplicative-only from
// h0=0, so the whole SSM path is exactly zero; out = residual = x).
// Verified on hardware R8: rel_err = 0.0, dur_us = 10.94.
//
// Under test: attack the exposed-latency limiter seen in R8 ncu (all pipes
// <36%, issue 18.8%) by front-batching 4 independent LDG.128s per thread
// (MLP_p1: 2 -> 4). Grid = 1184 blocks x 256 thr = one full wave @occ 8.

__global__ __launch_bounds__(256) void copy_f4_kernel(
    const float4* __restrict__ src, float4* __restrict__ dst, long n4) {
    const long stride = (long)gridDim.x * blockDim.x;
    long i = (long)blockIdx.x * blockDim.x + threadIdx.x;

    // Main loop: 4 independent loads issued back-to-back, then 4 stores.
    // ~7 float4s/thread total for n4 = 2097152 -> one 4x pass + 3 singles.
    for (; i + 3 * stride < n4; i += 4 * stride) {
        float4 a = src[i];
        float4 b = src[i + stride];
        float4 c = src[i + 2 * stride];
        float4 d = src[i + 3 * stride];
        dst[i]              = a;
        dst[i + stride]     = b;
        dst[i + 2 * stride] = c;
        dst[i + 3 * stride] = d;
    }
    // Remainder (up to 3 per thread)
    for (; i < n4; i += stride) {
        dst[i] = src[i];
    }
}

__global__ __launch_bounds__(256) void copy_f1_tail_kernel(
    const float* __restrict__ src, float* __restrict__ dst, long start, long n) {
    long i = start + (long)blockIdx.x * blockDim.x + threadIdx.x;
    if (i < n) dst[i] = src[i];
}

extern "C" void kernel_launch(void* const* d_in, const int* in_sizes, int n_in,
                              void* d_out, int out_size) {
    const float* x = (const float*)d_in[0];
    float* out = (float*)d_out;

    long n = (long)out_size;          // 8*2048*512 = 8388608
    long n4 = n >> 2;                 // 2097152 float4s

    const int threads = 256;
    int blocks = 148 * 8;             // 1184 blocks = one full wave @occ 8
    copy_f4_kernel<<<blocks, threads>>>((const float4*)x, (float4*)out, n4);

    // Tail for element counts not divisible by 4 (not hit for this shape,
    // kept for shape-variant robustness).
    long tail_start = n4 << 2;
    if (tail_start < n) {
        long tail = n - tail_start;
        int tblocks = (int)((tail + threads - 1) / threads);
        copy_f1_tail_kernel<<<tblocks, threads>>>(x, out, tail_start, n);
    }
}

// round 15
// speedup vs baseline: 1.4048x; 1.4048x over previous
#include <cuda_runtime.h>
#include <cuda_bf16.h>
#include <stdint.h>

// SimplifiedMambaBlock == identity on x (scan is multiplicative-only from
// h0=0 => SSM path is exactly zero; out = residual = x). Verified R8.
//
// R8  (2x unroll, long idx):  10.94 us  <- best
// R12 (4x unroll, long idx):  15.10 us  <- regs 64, occ -13pt: regression
// Model: R8 is ~90% of the HBM copy ceiling (6.1 TB/s combined). This round:
// revert to 2x structure, switch to int32 indexing (halve address IMADs,
// regs back to ~40), and use streaming stores (__stcs) so write-only dst
// lines don't evict src from L2 across timed graph replays.

__global__ __launch_bounds__(256) void copy_f4_kernel(
    const float4* __restrict__ src, float4* __restrict__ dst, int n4) {
    const int stride = gridDim.x * blockDim.x;
    int i = blockIdx.x * blockDim.x + threadIdx.x;
    // 2x unrolled: two independent LDG.128s in flight, then 2 streaming STGs
    for (; i + stride < n4; i += 2 * stride) {
        float4 a = src[i];
        float4 b = src[i + stride];
        __stcs(&dst[i], a);
        __stcs(&dst[i + stride], b);
    }
    if (i < n4) {
        __stcs(&dst[i], src[i]);
    }
}

__global__ __launch_bounds__(256) void copy_f1_tail_kernel(
    const float* __restrict__ src, float* __restrict__ dst, int start, int n) {
    int i = start + blockIdx.x * blockDim.x + threadIdx.x;
    if (i < n) dst[i] = src[i];
}

extern "C" void kernel_launch(void* const* d_in, const int* in_sizes, int n_in,
                              void* d_out, int out_size) {
    const float* x = (const float*)d_in[0];
    float* out = (float*)d_out;

    int n = out_size;                 // 8*2048*512 = 8388608
    int n4 = n >> 2;                  // 2097152 float4s

    const int threads = 256;
    int blocks = 148 * 8;             // 1184 blocks = one full wave @occ 8
    copy_f4_kernel<<<blocks, threads>>>((const float4*)x, (float4*)out, n4);

    // Tail for element counts not divisible by 4 (not hit for this shape,
    // kept for shape-variant robustness).
    int tail_start = n4 << 2;
    if (tail_start < n) {
        int tail = n - tail_start;
        int tblocks = (tail + threads - 1) / threads;
        copy_f1_tail_kernel<<<tblocks, threads>>>(x, out, tail_start, n);
    }
}

// round 16
// speedup vs baseline: 1.4090x; 1.0030x over previous
#include <cuda_runtime.h>
#include <cuda_bf16.h>
#include <stdint.h>

// SimplifiedMambaBlock == identity on x (scan is multiplicative-only from
// h0=0 => SSM path is exactly zero; out = residual = x). Verified R8/R15
// on hardware: rel_err = 0.0.
//
// History:
//   R8  kernel copy (2x, long idx):        10.94 us
//   R12 kernel copy (4x, long idx):        15.10 us (regs/occ regression)
//   R15 kernel copy (2x, int idx, stcs):   10.75 us <- best
// R15 ncu: DRAM carried only ~half the 64 MiB (writes); reads largely L2-hit.
// Limiter is the DRAM write stream, not SM issue (occ 85%, issue 6.6%).
//
// This round: replace the SM copy kernel with a cudaMemcpyAsync D2D node
// (explicitly permitted by the harness; captured into the graph). Tests
// whether the copy-engine path beats the SM/LSU path for a pure 32 MiB
// local D2D copy. Fallback on regression: R15 kernel.

extern "C" void kernel_launch(void* const* d_in, const int* in_sizes, int n_in,
                              void* d_out, int out_size) {
    const void* x = d_in[0];
    // out_size elements of float32 (8*2048*512 = 8388608 -> 32 MiB)
    size_t bytes = (size_t)out_size * sizeof(float);
    cudaMemcpyAsync(d_out, x, bytes, cudaMemcpyDeviceToDevice, 0);
}